// round 12
// baseline (speedup 1.0000x reference)
#include <cuda_runtime.h>
#include <math_constants.h>

// Sparse segment-max pooling, CSR two-pass, 4-rows-per-warp pool.
//   features : [N_IN, 32] f32, in_map : [E] i32, out_map : [E] i32 sorted,
//   out : [N_OUT, 32] f32 (empty segments -> 0)
//
// Pool: one warp owns 4 CONSECUTIVE output rows = 4 INDEPENDENT gather
// chains. One lane-load fetches the 5 CSR offsets; 4 independent coalesced
// in_map loads issue together; each chunk issues 4 rows x 8 edges = up to 32
// independent 128B feature-row loads (lane = channel) before folding.
// Chunk guards are warp-uniform. len>32 handled by a rare scalar loop.
// Each row stored once, coalesced. No atomics, no binary search.
// No thread exits before a warp shuffle anywhere (shuffle-safety).

#define MAX_NOUT (1 << 18)
#define RPW 4

__device__ int g_offsets[MAX_NOUT + 1];

__global__ __launch_bounds__(256)
void build_offsets(const int* __restrict__ out_map, int E, int n_out)
{
    const int e = blockIdx.x * blockDim.x + threadIdx.x;
    const bool active = (e < E);

    // Clamped load for active lanes only; inactive lanes carry a dummy.
    int o = active ? __ldg(&out_map[min(e, E - 1)]) : 0;
    if (o < 0) o = 0;
    if (o >= n_out) o = n_out - 1;

    // prev via warp shuffle (no lane has exited).
    int prev = __shfl_up_sync(0xffffffffu, o, 1);
    if (active && (threadIdx.x & 31) == 0)
        prev = (e == 0) ? -1 : min(max(__ldg(&out_map[e - 1]), 0), n_out - 1);

    if (active) {
        for (int r = prev + 1; r <= o; r++)
            g_offsets[r] = e;
        if (e == E - 1)
            for (int r = o + 1; r <= n_out; r++)
                g_offsets[r] = E;
    }
}

__global__ __launch_bounds__(256)
void sparse_pool_kernel(const float* __restrict__ features,
                        const int*   __restrict__ in_map,
                        float*       __restrict__ out,
                        int E, int n_out)
{
    const unsigned FULL = 0xffffffffu;
    const float NI = -CUDART_INF_F;

    const int warp_global = (blockIdx.x * blockDim.x + threadIdx.x) >> 5;
    const int lane = threadIdx.x & 31;
    const int row0 = warp_global * RPW;
    const bool wactive = (row0 < n_out);   // warp-uniform

    // One coalesced load: lane l holds g_offsets[row0 + l] (first 5 used).
    // Inactive warps read g_offsets[n_out] (valid address) -> len 0.
    const int off = __ldg(&g_offsets[wactive ? min(row0 + lane, n_out) : n_out]);

    int s[RPW], len[RPW];
    #pragma unroll
    for (int r = 0; r < RPW; r++) {
        s[r] = __shfl_sync(FULL, off, r);
        len[r] = __shfl_sync(FULL, off, r + 1) - s[r];
    }

    // 4 independent coalesced index loads (first 32 edges of each row).
    int idx[RPW];
    #pragma unroll
    for (int r = 0; r < RPW; r++)
        idx[r] = (lane < min(len[r], 32)) ? __ldg(&in_map[s[r] + lane]) : 0;

    float m[RPW];
    #pragma unroll
    for (int r = 0; r < RPW; r++) m[r] = NI;

    const int lenmax = max(max(len[0], len[1]), max(len[2], len[3]));

    // Chunk loop: edges [J, J+8) of all 4 rows. Guard is warp-uniform, so
    // whole chunks are skipped for short segments (Poisson(15.3) tail).
    for (int J = 0; J < 32; J += 8) {
        if (J >= lenmax) break;
        float f[RPW][8];
        #pragma unroll
        for (int r = 0; r < RPW; r++) {
            #pragma unroll
            for (int j = 0; j < 8; j++) {
                if (J + j < len[r]) {
                    int ri = __shfl_sync(FULL, idx[r], (J + j) & 31);
                    f[r][j] = __ldg(&features[(size_t)ri * 32 + lane]);
                }
            }
        }
        #pragma unroll
        for (int r = 0; r < RPW; r++) {
            #pragma unroll
            for (int j = 0; j < 8; j++)
                if (J + j < len[r]) m[r] = fmaxf(m[r], f[r][j]);
        }
    }

    // Extremely rare: segments longer than 32 edges.
    if (lenmax > 32) {
        #pragma unroll
        for (int r = 0; r < RPW; r++) {
            const int e_end = min(s[r] + len[r], E);
            for (int e = s[r] + 32; e < e_end; e++) {
                int ri = __ldg(&in_map[e]);
                m[r] = fmaxf(m[r], __ldg(&features[(size_t)ri * 32 + lane]));
            }
        }
    }

    // Store each row once; empty segment -> 0.
    if (wactive) {
        #pragma unroll
        for (int r = 0; r < RPW; r++) {
            if (row0 + r < n_out)
                out[(size_t)(row0 + r) * 32 + lane] = (len[r] > 0) ? m[r] : 0.0f;
        }
    }
}

extern "C" void kernel_launch(void* const* d_in, const int* in_sizes, int n_in,
                              void* d_out, int out_size)
{
    const float* features = (const float*)d_in[0];
    const int*   in_map   = (const int*)d_in[1];
    const int*   out_map  = (const int*)d_in[2];
    float* out = (float*)d_out;

    const int E = in_sizes[1];
    int n_out = out_size / 32;
    if (n_out > MAX_NOUT) n_out = MAX_NOUT;

    {
        const int threads = 256;
        const int blocks = (E + threads - 1) / threads;
        build_offsets<<<blocks, threads>>>(out_map, E, n_out);
    }
    {
        const int threads = 256;  // 8 warps/block
        const int warps = (n_out + RPW - 1) / RPW;
        const int blocks = (warps * 32 + threads - 1) / threads;
        sparse_pool_kernel<<<blocks, threads>>>(features, in_map, out, E, n_out);
    }
}

// round 13
// speedup vs baseline: 2.8758x; 2.8758x over previous
#include <cuda_runtime.h>
#include <math_constants.h>

// Sparse segment-max pooling, CSR two-pass. Pool = warp-per-row (the proven
// R5 structure) with a depth-16 register gather pipeline.
//   features : [N_IN, 32] f32, in_map : [E] i32, out_map : [E] i32 sorted,
//   out : [N_OUT, 32] f32 (empty segments -> 0)
//
// Pool: one warp per output row, lane = channel. Two coalesced offset loads,
// ONE coalesced in_map load (covers up to 32 edges; avg segment = 15.3).
// Batch 1 issues up to 16 independent 128B feature-row gathers before any
// fold (P(len<=16) ~ 0.62 -> whole segment in one memory round-trip).
// Batch 2 (edges 16..31) under a warp-uniform guard; len>32 rare scalar tail.
// One coalesced 128B store per row. No atomics, no binary search.

#define MAX_NOUT (1 << 18)

__device__ int g_offsets[MAX_NOUT + 1];

__global__ __launch_bounds__(256)
void build_offsets(const int* __restrict__ out_map, int E, int n_out)
{
    const int e = blockIdx.x * blockDim.x + threadIdx.x;
    const bool active = (e < E);

    int o = active ? __ldg(&out_map[min(e, E - 1)]) : 0;
    if (o < 0) o = 0;
    if (o >= n_out) o = n_out - 1;

    // prev via warp shuffle: halves out_map read traffic.
    int prev = __shfl_up_sync(0xffffffffu, o, 1);
    if (active && (threadIdx.x & 31) == 0)
        prev = (e == 0) ? -1 : min(max(__ldg(&out_map[e - 1]), 0), n_out - 1);

    if (active) {
        for (int r = prev + 1; r <= o; r++)
            g_offsets[r] = e;
        if (e == E - 1)
            for (int r = o + 1; r <= n_out; r++)
                g_offsets[r] = E;
    }
}

__global__ __launch_bounds__(256)
void sparse_pool_kernel(const float* __restrict__ features,
                        const int*   __restrict__ in_map,
                        float*       __restrict__ out,
                        int E, int n_out)
{
    const unsigned FULL = 0xffffffffu;
    const float NI = -CUDART_INF_F;

    const int warp_global = (blockIdx.x * blockDim.x + threadIdx.x) >> 5;
    const int lane = threadIdx.x & 31;
    const bool wactive = (warp_global < n_out);   // warp-uniform

    const int target = wactive ? warp_global : (n_out - 1);

    // Coalesced offset loads (consecutive warps -> consecutive addresses).
    const int start = __ldg(&g_offsets[target]);
    const int end   = __ldg(&g_offsets[target + 1]);
    const int len   = end - start;

    // One coalesced load covers up to 32 edge indices.
    const int idx = (lane < min(len, 32)) ? __ldg(&in_map[start + lane]) : 0;

    float m = NI;

    // ---- Batch 1: edges [0,16) — 16 independent gathers in flight. ----
    {
        float f[16];
        #pragma unroll
        for (int j = 0; j < 16; j++) {
            int r = __shfl_sync(FULL, idx, j);
            f[j] = (j < len) ? __ldg(&features[(size_t)r * 32 + lane]) : NI;
        }
        // Pairwise tree fold.
        #pragma unroll
        for (int st = 8; st >= 1; st >>= 1)
            #pragma unroll
            for (int j = 0; j < 16; j++)
                if (j < st) f[j] = fmaxf(f[j], f[j + st]);
        m = f[0];
    }

    // ---- Batch 2: edges [16,32) — warp-uniform guard (P(len>16)~0.38). ----
    if (len > 16) {
        float f[16];
        #pragma unroll
        for (int j = 0; j < 16; j++) {
            int r = __shfl_sync(FULL, idx, 16 + j);
            f[j] = (16 + j < len) ? __ldg(&features[(size_t)r * 32 + lane]) : NI;
        }
        #pragma unroll
        for (int st = 8; st >= 1; st >>= 1)
            #pragma unroll
            for (int j = 0; j < 16; j++)
                if (j < st) f[j] = fmaxf(f[j], f[j + st]);
        m = fmaxf(m, f[0]);
    }

    // ---- Rare tail: segments longer than 32 edges. ----
    if (len > 32) {
        const int e_end = min(end, E);
        for (int e = start + 32; e < e_end; e++) {
            int r = __ldg(&in_map[e]);
            m = fmaxf(m, __ldg(&features[(size_t)r * 32 + lane]));
        }
    }

    // Empty segment -> 0 (reference maps -inf to 0). Store once, coalesced.
    if (wactive)
        out[(size_t)target * 32 + lane] = (len > 0) ? m : 0.0f;
}

extern "C" void kernel_launch(void* const* d_in, const int* in_sizes, int n_in,
                              void* d_out, int out_size)
{
    const float* features = (const float*)d_in[0];
    const int*   in_map   = (const int*)d_in[1];
    const int*   out_map  = (const int*)d_in[2];
    float* out = (float*)d_out;

    const int E = in_sizes[1];
    int n_out = out_size / 32;
    if (n_out > MAX_NOUT) n_out = MAX_NOUT;

    {
        const int threads = 256;
        const int blocks = (E + threads - 1) / threads;
        build_offsets<<<blocks, threads>>>(out_map, E, n_out);
    }
    {
        const int threads = 256;  // 8 warps/block, one warp per output row
        const int blocks = (n_out * 32 + threads - 1) / threads;
        sparse_pool_kernel<<<blocks, threads>>>(features, in_map, out, E, n_out);
    }
}

// round 15
// speedup vs baseline: 3.8399x; 1.3353x over previous
#include <cuda_runtime.h>
#include <cuda_pipeline.h>
#include <math_constants.h>

// Sparse segment-max pooling, CSR two-pass, cp.async-staged pool.
//   features : [N_IN, 32] f32, in_map : [E] i32, out_map : [E] i32 sorted,
//   out : [N_OUT, 32] f32 (empty segments -> 0)
//
// Pool: one warp per output row. Feature-row gathers are staged into shared
// memory with cp.async (LDGSTS, 16B per lane: one instruction moves 4 rows =
// 512B). Up to 16 rows (2KB) in flight per warp with ZERO register cost
// (async-group tracking, no scoreboard registers), then folded from smem.
// Round 2 covers edges 16..31 under a warp-uniform guard; len>32 rare scalar
// tail. launch_bounds(256,8) pins regs<=32 -> ~64 warps/SM.

#define MAX_NOUT (1 << 18)

__device__ int g_offsets[MAX_NOUT + 1];

__global__ __launch_bounds__(256)
void build_offsets(const int* __restrict__ out_map, int E, int n_out)
{
    const int e = blockIdx.x * blockDim.x + threadIdx.x;
    const bool active = (e < E);

    int o = active ? __ldg(&out_map[min(e, E - 1)]) : 0;
    if (o < 0) o = 0;
    if (o >= n_out) o = n_out - 1;

    // prev via warp shuffle: halves out_map read traffic.
    int prev = __shfl_up_sync(0xffffffffu, o, 1);
    if (active && (threadIdx.x & 31) == 0)
        prev = (e == 0) ? -1 : min(max(__ldg(&out_map[e - 1]), 0), n_out - 1);

    if (active) {
        for (int r = prev + 1; r <= o; r++)
            g_offsets[r] = e;
        if (e == E - 1)
            for (int r = o + 1; r <= n_out; r++)
                g_offsets[r] = E;
    }
}

__global__ __launch_bounds__(256, 8)
void sparse_pool_kernel(const float* __restrict__ features,
                        const int*   __restrict__ in_map,
                        float*       __restrict__ out,
                        int E, int n_out)
{
    __shared__ float buf[8][16][32];   // 16 KB: per-warp 16-row staging tile

    const unsigned FULL = 0xffffffffu;
    const float NI = -CUDART_INF_F;

    const int warp = threadIdx.x >> 5;
    const int lane = threadIdx.x & 31;
    const int warp_global = blockIdx.x * 8 + warp;
    const bool wactive = (warp_global < n_out);      // warp-uniform

    const int target = wactive ? warp_global : (n_out - 1);

    // Coalesced offset loads (consecutive warps -> consecutive addresses).
    const int start = __ldg(&g_offsets[target]);
    const int end   = __ldg(&g_offsets[target + 1]);
    const int len   = end - start;

    // One coalesced load covers up to 32 edge indices.
    const int idx = (lane < min(len, 32)) ? __ldg(&in_map[start + lane]) : 0;

    const int g  = lane >> 3;          // row-group within a 4-row pack
    const int c0 = (lane & 7) * 4;     // channel base of this lane's 16B

    float m = NI;

    // Two staging rounds: edges [0,16) and [16,32). Guards warp-uniform.
    #pragma unroll
    for (int R = 0; R < 2; R++) {
        const int J = R * 16;
        if (len <= J) break;
        const int cnt = min(len - J, 16);

        // Stage cnt rows: ceil(cnt/4) LDGSTS per lane-group, 4 rows each.
        #pragma unroll
        for (int jj = 0; jj < 16; jj += 4) {
            if (jj >= cnt) break;                    // warp-uniform
            const int row = jj + g;                  // 0..15 within round
            const int r = __shfl_sync(FULL, idx, (J + row) & 31);
            if (row < cnt) {
                __pipeline_memcpy_async(&buf[warp][row][c0],
                                        features + (size_t)r * 32 + c0,
                                        16);
            }
        }
        __pipeline_commit();
        __pipeline_wait_prior(0);
        __syncwarp();

        // Fold from smem: lane = channel, conflict-free.
        int j = 0;
        for (; j + 4 <= cnt; j += 4) {
            float a = buf[warp][j + 0][lane];
            float b = buf[warp][j + 1][lane];
            float c = buf[warp][j + 2][lane];
            float d = buf[warp][j + 3][lane];
            m = fmaxf(m, fmaxf(fmaxf(a, b), fmaxf(c, d)));
        }
        for (; j < cnt; j++)
            m = fmaxf(m, buf[warp][j][lane]);
        __syncwarp();                                // buf reuse safety
    }

    // Rare tail: segments longer than 32 edges.
    if (len > 32) {
        const int e_end = min(end, E);
        for (int e = start + 32; e < e_end; e++) {
            int r = __ldg(&in_map[e]);
            m = fmaxf(m, __ldg(&features[(size_t)r * 32 + lane]));
        }
    }

    // Empty segment -> 0 (reference maps -inf to 0). One coalesced store.
    if (wactive)
        out[(size_t)target * 32 + lane] = (len > 0) ? m : 0.0f;
}

extern "C" void kernel_launch(void* const* d_in, const int* in_sizes, int n_in,
                              void* d_out, int out_size)
{
    const float* features = (const float*)d_in[0];
    const int*   in_map   = (const int*)d_in[1];
    const int*   out_map  = (const int*)d_in[2];
    float* out = (float*)d_out;

    const int E = in_sizes[1];
    int n_out = out_size / 32;
    if (n_out > MAX_NOUT) n_out = MAX_NOUT;

    {
        const int threads = 256;
        const int blocks = (E + threads - 1) / threads;
        build_offsets<<<blocks, threads>>>(out_map, E, n_out);
    }
    {
        const int threads = 256;  // 8 warps/block, one warp per output row
        const int blocks = (n_out + 7) / 8;
        sparse_pool_kernel<<<blocks, threads>>>(features, in_map, out, E, n_out);
    }
}

// round 16
// speedup vs baseline: 3.9085x; 1.0179x over previous
#include <cuda_runtime.h>
#include <cuda_pipeline.h>
#include <math_constants.h>

// Sparse segment-max pooling, CSR two-pass, double-buffered cp.async pool.
//   features : [N_IN, 32] f32, in_map : [E] i32, out_map : [E] i32 sorted,
//   out : [N_OUT, 32] f32 (empty segments -> 0)
//
// Pool: one warp per output row. All (up to) 32 feature-row gathers are
// issued as cp.async (LDGSTS, 16B/lane) in TWO commit-groups up front —
// 4KB in flight per warp, zero register cost. wait_prior(1) lets the fold of
// rows 0..15 overlap the in-flight rows 16..31. len>32 rare scalar tail.
// smem 32KB/block -> 7 blocks/SM (~56 warps). regs pinned ~32.
//
// Pass A: int4-vectorized boundary detection (4 edges/thread).

#define MAX_NOUT (1 << 18)

__device__ int g_offsets[MAX_NOUT + 1];

__global__ __launch_bounds__(256)
void build_offsets(const int* __restrict__ out_map, int E, int n_out)
{
    const unsigned FULL = 0xffffffffu;
    const int t = blockIdx.x * blockDim.x + threadIdx.x;
    const int e0 = t * 4;
    const bool active = (e0 < E);

    int o[4];
    if (active) {
        if (e0 + 3 < E) {
            int4 v = __ldg(((const int4*)out_map) + t);
            o[0] = v.x; o[1] = v.y; o[2] = v.z; o[3] = v.w;
        } else {
            #pragma unroll
            for (int j = 0; j < 4; j++)
                o[j] = __ldg(&out_map[min(e0 + j, E - 1)]);
        }
        #pragma unroll
        for (int j = 0; j < 4; j++)
            o[j] = min(max(o[j], 0), n_out - 1);
    } else {
        o[0] = o[1] = o[2] = o[3] = 0;
    }

    // prev = out_map[e0-1]: previous thread's last element via shuffle;
    // lane 0 loads it (one scalar load per warp).
    int prev = __shfl_up_sync(FULL, o[3], 1);
    if (active && (threadIdx.x & 31) == 0)
        prev = (e0 == 0) ? -1 : min(max(__ldg(&out_map[e0 - 1]), 0), n_out - 1);

    if (active) {
        int p = prev;
        #pragma unroll
        for (int j = 0; j < 4; j++) {
            if (e0 + j < E) {
                for (int r = p + 1; r <= o[j]; r++)
                    g_offsets[r] = e0 + j;
                p = o[j];
            }
        }
        // Thread owning the last edge closes the CSR.
        if (e0 <= E - 1 && E - 1 < e0 + 4) {
            const int olast = o[min(3, E - 1 - e0)];
            for (int r = olast + 1; r <= n_out; r++)
                g_offsets[r] = E;
        }
    }
}

__global__ __launch_bounds__(256, 7)
void sparse_pool_kernel(const float* __restrict__ features,
                        const int*   __restrict__ in_map,
                        float*       __restrict__ out,
                        int E, int n_out)
{
    __shared__ float buf[8][32][32];   // 32 KB: per-warp 32-row staging tile

    const unsigned FULL = 0xffffffffu;
    const float NI = -CUDART_INF_F;

    const int warp = threadIdx.x >> 5;
    const int lane = threadIdx.x & 31;
    const int warp_global = blockIdx.x * 8 + warp;
    const bool wactive = (warp_global < n_out);      // warp-uniform

    const int target = wactive ? warp_global : (n_out - 1);

    // Coalesced offset loads (consecutive warps -> consecutive addresses).
    const int start = __ldg(&g_offsets[target]);
    const int end   = __ldg(&g_offsets[target + 1]);
    const int len   = end - start;

    // One coalesced load covers up to 32 edge indices.
    const int idx = (lane < min(len, 32)) ? __ldg(&in_map[start + lane]) : 0;

    const int g  = lane >> 3;          // row-group within a 4-row pack
    const int c0 = (lane & 7) * 4;     // channel base of this lane's 16B

    const int cnt1 = min(len, 16);
    const int cnt2 = min(max(len - 16, 0), 16);

    // ---- Issue ALL gathers up front: two commit-groups, 4KB in flight. ----
    #pragma unroll
    for (int jj = 0; jj < 16; jj += 4) {
        if (jj >= cnt1) break;                       // warp-uniform
        const int row = jj + g;
        const int r = __shfl_sync(FULL, idx, row & 31);
        if (row < cnt1)
            __pipeline_memcpy_async(&buf[warp][row][c0],
                                    features + (size_t)r * 32 + c0, 16);
    }
    __pipeline_commit();                              // group A: rows 0..15

    #pragma unroll
    for (int jj = 0; jj < 16; jj += 4) {
        if (jj >= cnt2) break;                       // warp-uniform
        const int row = jj + g;
        const int r = __shfl_sync(FULL, idx, (16 + row) & 31);
        if (row < cnt2)
            __pipeline_memcpy_async(&buf[warp][16 + row][c0],
                                    features + (size_t)r * 32 + c0, 16);
    }
    __pipeline_commit();                              // group B: rows 16..31

    float m = NI;

    // ---- Fold rows 0..15 while group B is still in flight. ----
    __pipeline_wait_prior(1);
    __syncwarp();
    {
        int j = 0;
        for (; j + 4 <= cnt1; j += 4) {
            float a = buf[warp][j + 0][lane];
            float b = buf[warp][j + 1][lane];
            float c = buf[warp][j + 2][lane];
            float d = buf[warp][j + 3][lane];
            m = fmaxf(m, fmaxf(fmaxf(a, b), fmaxf(c, d)));
        }
        for (; j < cnt1; j++)
            m = fmaxf(m, buf[warp][j][lane]);
    }

    // ---- Fold rows 16..31. ----
    __pipeline_wait_prior(0);
    __syncwarp();
    {
        int j = 0;
        for (; j + 4 <= cnt2; j += 4) {
            float a = buf[warp][16 + j + 0][lane];
            float b = buf[warp][16 + j + 1][lane];
            float c = buf[warp][16 + j + 2][lane];
            float d = buf[warp][16 + j + 3][lane];
            m = fmaxf(m, fmaxf(fmaxf(a, b), fmaxf(c, d)));
        }
        for (; j < cnt2; j++)
            m = fmaxf(m, buf[warp][16 + j][lane]);
    }

    // Rare tail: segments longer than 32 edges.
    if (len > 32) {
        const int e_end = min(end, E);
        for (int e = start + 32; e < e_end; e++) {
            int r = __ldg(&in_map[e]);
            m = fmaxf(m, __ldg(&features[(size_t)r * 32 + lane]));
        }
    }

    // Empty segment -> 0 (reference maps -inf to 0). One coalesced store.
    if (wactive)
        out[(size_t)target * 32 + lane] = (len > 0) ? m : 0.0f;
}

extern "C" void kernel_launch(void* const* d_in, const int* in_sizes, int n_in,
                              void* d_out, int out_size)
{
    const float* features = (const float*)d_in[0];
    const int*   in_map   = (const int*)d_in[1];
    const int*   out_map  = (const int*)d_in[2];
    float* out = (float*)d_out;

    const int E = in_sizes[1];
    int n_out = out_size / 32;
    if (n_out > MAX_NOUT) n_out = MAX_NOUT;

    {
        const int threads = 256;                 // 4 edges per thread
        const int blocks = (E / 4 + threads) / threads + 1;
        build_offsets<<<blocks, threads>>>(out_map, E, n_out);
    }
    {
        const int threads = 256;  // 8 warps/block, one warp per output row
        const int blocks = (n_out + 7) / 8;
        sparse_pool_kernel<<<blocks, threads>>>(features, in_map, out, E, n_out);
    }
}

// round 17
// speedup vs baseline: 4.4640x; 1.1421x over previous
#include <cuda_runtime.h>
#include <cuda_pipeline.h>
#include <math_constants.h>

// Sparse segment-max pooling, CSR two-pass, cp.async pool (24-row buffer).
//   features : [N_IN, 32] f32, in_map : [E] i32, out_map : [E] i32 sorted,
//   out : [N_OUT, 32] f32 (empty segments -> 0)
//
// Pool: one warp per output row. Up to 24 feature-row gathers issued up
// front as cp.async (LDGSTS, 16B/lane) in TWO commit-groups (rows 0..15,
// rows 16..23); fold of group A overlaps group B's flight. 24KB smem/block
// -> 8 blocks/SM (64 warps, RF exactly full at 32 regs). len>24 (~1.3% of
// warps) finishes with a batched scalar tail. No atomics, no binary search.
//
// Pass A: int4-vectorized boundary detection (4 edges/thread).

#define MAX_NOUT (1 << 18)

__device__ int g_offsets[MAX_NOUT + 1];

__global__ __launch_bounds__(256)
void build_offsets(const int* __restrict__ out_map, int E, int n_out)
{
    const unsigned FULL = 0xffffffffu;
    const int t = blockIdx.x * blockDim.x + threadIdx.x;
    const int e0 = t * 4;
    const bool active = (e0 < E);

    int o[4];
    if (active) {
        if (e0 + 3 < E) {
            int4 v = __ldg(((const int4*)out_map) + t);
            o[0] = v.x; o[1] = v.y; o[2] = v.z; o[3] = v.w;
        } else {
            #pragma unroll
            for (int j = 0; j < 4; j++)
                o[j] = __ldg(&out_map[min(e0 + j, E - 1)]);
        }
        #pragma unroll
        for (int j = 0; j < 4; j++)
            o[j] = min(max(o[j], 0), n_out - 1);
    } else {
        o[0] = o[1] = o[2] = o[3] = 0;
    }

    // prev = out_map[e0-1]: previous thread's last element via shuffle;
    // lane 0 loads it (one scalar load per warp).
    int prev = __shfl_up_sync(FULL, o[3], 1);
    if (active && (threadIdx.x & 31) == 0)
        prev = (e0 == 0) ? -1 : min(max(__ldg(&out_map[e0 - 1]), 0), n_out - 1);

    if (active) {
        int p = prev;
        #pragma unroll
        for (int j = 0; j < 4; j++) {
            if (e0 + j < E) {
                for (int r = p + 1; r <= o[j]; r++)
                    g_offsets[r] = e0 + j;
                p = o[j];
            }
        }
        // Thread owning the last edge closes the CSR.
        if (e0 <= E - 1 && E - 1 < e0 + 4) {
            const int olast = o[min(3, E - 1 - e0)];
            for (int r = olast + 1; r <= n_out; r++)
                g_offsets[r] = E;
        }
    }
}

__global__ __launch_bounds__(256, 8)
void sparse_pool_kernel(const float* __restrict__ features,
                        const int*   __restrict__ in_map,
                        float*       __restrict__ out,
                        int E, int n_out)
{
    __shared__ float buf[8][24][32];   // 24 KB: per-warp 24-row staging tile

    const unsigned FULL = 0xffffffffu;
    const float NI = -CUDART_INF_F;

    const int warp = threadIdx.x >> 5;
    const int lane = threadIdx.x & 31;
    const int warp_global = blockIdx.x * 8 + warp;
    const bool wactive = (warp_global < n_out);      // warp-uniform

    const int target = wactive ? warp_global : (n_out - 1);

    // Coalesced offset loads (consecutive warps -> consecutive addresses).
    const int start = __ldg(&g_offsets[target]);
    const int end   = __ldg(&g_offsets[target + 1]);
    const int len   = end - start;

    // One coalesced load covers up to 32 edge indices (24 used for staging).
    const int idx = (lane < min(len, 32)) ? __ldg(&in_map[start + lane]) : 0;

    const int g  = lane >> 3;          // row-group within a 4-row pack
    const int c0 = (lane & 7) * 4;     // channel base of this lane's 16B

    const int cnt1 = min(len, 16);
    const int cnt2 = min(max(len - 16, 0), 8);

    // ---- Issue all staged gathers up front: two commit-groups (3KB). ----
    #pragma unroll
    for (int jj = 0; jj < 16; jj += 4) {
        if (jj >= cnt1) break;                       // warp-uniform
        const int row = jj + g;
        const int r = __shfl_sync(FULL, idx, row & 31);
        if (row < cnt1)
            __pipeline_memcpy_async(&buf[warp][row][c0],
                                    features + (size_t)r * 32 + c0, 16);
    }
    __pipeline_commit();                              // group A: rows 0..15

    #pragma unroll
    for (int jj = 0; jj < 8; jj += 4) {
        if (jj >= cnt2) break;                       // warp-uniform
        const int row = jj + g;
        const int r = __shfl_sync(FULL, idx, (16 + row) & 31);
        if (row < cnt2)
            __pipeline_memcpy_async(&buf[warp][16 + row][c0],
                                    features + (size_t)r * 32 + c0, 16);
    }
    __pipeline_commit();                              // group B: rows 16..23

    float m = NI;

    // ---- Fold rows 0..15 while group B is still in flight. ----
    __pipeline_wait_prior(1);
    __syncwarp();
    {
        int j = 0;
        for (; j + 4 <= cnt1; j += 4) {
            float a = buf[warp][j + 0][lane];
            float b = buf[warp][j + 1][lane];
            float c = buf[warp][j + 2][lane];
            float d = buf[warp][j + 3][lane];
            m = fmaxf(m, fmaxf(fmaxf(a, b), fmaxf(c, d)));
        }
        for (; j < cnt1; j++)
            m = fmaxf(m, buf[warp][j][lane]);
    }

    // ---- Fold rows 16..23. ----
    __pipeline_wait_prior(0);
    __syncwarp();
    {
        int j = 0;
        for (; j + 4 <= cnt2; j += 4) {
            float a = buf[warp][16 + j + 0][lane];
            float b = buf[warp][16 + j + 1][lane];
            float c = buf[warp][16 + j + 2][lane];
            float d = buf[warp][16 + j + 3][lane];
            m = fmaxf(m, fmaxf(fmaxf(a, b), fmaxf(c, d)));
        }
        for (; j < cnt2; j++)
            m = fmaxf(m, buf[warp][16 + j][lane]);
    }

    // Rare tail (~1.3% of warps): edges 24..len-1 via batched scalar LDGs.
    if (len > 24) {
        const int e_end = min(end, E);
        int e = start + 24;
        for (; e + 4 <= e_end; e += 4) {
            int r0 = __ldg(&in_map[e + 0]);
            int r1 = __ldg(&in_map[e + 1]);
            int r2 = __ldg(&in_map[e + 2]);
            int r3 = __ldg(&in_map[e + 3]);
            float a = __ldg(&features[(size_t)r0 * 32 + lane]);
            float b = __ldg(&features[(size_t)r1 * 32 + lane]);
            float c = __ldg(&features[(size_t)r2 * 32 + lane]);
            float d = __ldg(&features[(size_t)r3 * 32 + lane]);
            m = fmaxf(m, fmaxf(fmaxf(a, b), fmaxf(c, d)));
        }
        for (; e < e_end; e++) {
            int r = __ldg(&in_map[e]);
            m = fmaxf(m, __ldg(&features[(size_t)r * 32 + lane]));
        }
    }

    // Empty segment -> 0 (reference maps -inf to 0). One coalesced store.
    if (wactive)
        out[(size_t)target * 32 + lane] = (len > 0) ? m : 0.0f;
}

extern "C" void kernel_launch(void* const* d_in, const int* in_sizes, int n_in,
                              void* d_out, int out_size)
{
    const float* features = (const float*)d_in[0];
    const int*   in_map   = (const int*)d_in[1];
    const int*   out_map  = (const int*)d_in[2];
    float* out = (float*)d_out;

    const int E = in_sizes[1];
    int n_out = out_size / 32;
    if (n_out > MAX_NOUT) n_out = MAX_NOUT;

    {
        const int threads = 256;                 // 4 edges per thread
        const int blocks = (E / 4 + threads) / threads + 1;
        build_offsets<<<blocks, threads>>>(out_map, E, n_out);
    }
    {
        const int threads = 256;  // 8 warps/block, one warp per output row
        const int blocks = (n_out + 7) / 8;
        sparse_pool_kernel<<<blocks, threads>>>(features, in_map, out, E, n_out);
    }
}